// round 14
// baseline (speedup 1.0000x reference)
#include <cuda_runtime.h>
#include <stdint.h>

// GINGCN forward, single persistent kernel with grid-wide barriers.
//   out[r] = (1+eps)*x[r] + dis_r * sum_{e: row==r} rsqrt(deg[col]) * x[col]
//
// Phases (all in one launch, full-residency grid, sense-reversing barriers):
//   P0 zero deg/cnt, reset ovf count, detect edge dtype (int64 vs int32)
//   -- grid barrier --
//   P1 build: one edge pass; atomicAdd deg[col]; append col to bucket[row];
//      overflow -> global (r,c) list (statistically never at mean degree 16)
//   -- grid barrier --
//   P2 gather (R7 shape, unchanged): 1 warp/node grid-stride, lane owns 4
//      features; bucket cols broadcast via shfl; x[col] gathered as float4
//   P3 overflow drain: only if g_ovf_n != 0 (needs 3rd barrier then atomics);
//      common case reads the (build-phase-stable) count and exits barrier-free.

#define N_MAX   100000
#define D       128
#define D4      (D / 4)        // 32 float4 per row
#define CAP     64
#define OVF_MAX 2000000

__device__ int      g_deg[N_MAX];                  // in-degree (col counts)
__device__ int      g_cnt[N_MAX];                  // per-row bucket fill counts
__device__ int      g_bkt[(size_t)N_MAX * CAP];    // bucket: col only
__device__ int      g_is64;                        // edge dtype flag
__device__ int      g_ovf_n;                       // overflow entry count
__device__ int2     g_ovf[OVF_MAX];                // overflow: {row, col}
__device__ unsigned g_bar_cnt = 0;                 // barrier arrival counter
__device__ volatile unsigned g_bar_gen = 0;        // barrier generation (sense)

// ------------------------------------------------------- grid-wide barrier
// Sense-reversing, self-resetting; safe because the grid is sized to full
// residency (all blocks co-resident). Re-entrant across graph replays.
__device__ __forceinline__ void grid_barrier() {
    __syncthreads();
    if (threadIdx.x == 0) {
        __threadfence();
        unsigned gen = g_bar_gen;
        unsigned arrived = atomicAdd(&g_bar_cnt, 1u) + 1u;
        if (arrived == gridDim.x) {
            g_bar_cnt = 0;
            __threadfence();
            g_bar_gen = gen + 1u;          // release
        } else {
            while (g_bar_gen == gen) { }   // spin (HW coherent via L2)
        }
        __threadfence();
    }
    __syncthreads();
}

// ---------------------------------------------------------------- edge access
__device__ __forceinline__ int edge_val(const void* ei, size_t idx, int is64) {
    if (is64) return (int)((const long long*)ei)[idx];
    return ((const int*)ei)[idx];
}

// ---------------------------------------------------------------- fused kernel
__global__ void __launch_bounds__(256, 8)
k_fused(const float4* __restrict__ x4, float4* __restrict__ o4,
        const float* __restrict__ eps, const void* __restrict__ ei,
        int n, int E) {
    int tid      = blockIdx.x * blockDim.x + threadIdx.x;
    int nthreads = gridDim.x * blockDim.x;

    // ---- P0: zero counters + detect dtype --------------------------------
    for (int i = tid; i < n; i += nthreads) { g_deg[i] = 0; g_cnt[i] = 0; }
    if (tid == 0) {
        g_ovf_n = 0;
        // int64 little-endian values < 2^31 -> every odd int32 word is 0.
        const int* p = (const int*)ei;
        int nz = 0;
        #pragma unroll
        for (int k = 0; k < 64; k++) nz |= p[2 * k + 1];
        g_is64 = (nz == 0) ? 1 : 0;
    }
    grid_barrier();

    // ---- P1: build (count + bucket fill, one edge pass) ------------------
    {
        int is64 = g_is64;
        for (int e = tid; e < E; e += nthreads) {
            int r = edge_val(ei, (size_t)e, is64);
            int c = edge_val(ei, (size_t)E + e, is64);
            atomicAdd(&g_deg[c], 1);
            int slot = atomicAdd(&g_cnt[r], 1);
            if (slot < CAP) {
                g_bkt[(size_t)r * CAP + slot] = c;
            } else {
                int o = atomicAdd(&g_ovf_n, 1);
                if (o < OVF_MAX) g_ovf[o] = make_int2(r, c);
            }
        }
    }
    grid_barrier();

    // ---- P2: gather (R7 inner loop, grid-stride over nodes) --------------
    {
        int gwarp = tid >> 5;
        int nwarp = nthreads >> 5;
        int lane  = threadIdx.x & 31;
        float s   = 1.0f + eps[0];

        for (int w = gwarp; w < n; w += nwarp) {
            int cnt = g_cnt[w];
            if (cnt > CAP) cnt = CAP;

            float4 xv = x4[(size_t)w * D4 + lane];
            float4 acc;
            acc.x = s * xv.x; acc.y = s * xv.y; acc.z = s * xv.z; acc.w = s * xv.w;

            int   dw    = g_deg[w];
            float dis_w = (dw > 0) ? rsqrtf((float)dw) : 0.0f;

            size_t base = (size_t)w * CAP;
            for (int j0 = 0; j0 < cnt; j0 += 32) {
                int   mycol = 0;
                float mynrm = 0.0f;
                int idx = j0 + lane;
                if (idx < cnt) {
                    mycol = g_bkt[base + idx];
                    mynrm = dis_w * rsqrtf((float)g_deg[mycol]);
                }
                int m = min(32, cnt - j0);

                #pragma unroll 4
                for (int j = 0; j < m; j++) {
                    int   c  = __shfl_sync(0xffffffffu, mycol, j);
                    float nm = __shfl_sync(0xffffffffu, mynrm, j);
                    float4 v = x4[(size_t)c * D4 + lane];
                    acc.x += nm * v.x;
                    acc.y += nm * v.y;
                    acc.z += nm * v.z;
                    acc.w += nm * v.w;
                }
            }
            o4[(size_t)w * D4 + lane] = acc;
        }
    }

    // ---- P3: overflow drain (common case: count==0, exit barrier-free) ---
    // g_ovf_n was finalized in P1 (before barrier 2) -> stable to read here.
    int nov = g_ovf_n;
    if (nov == 0) return;
    if (nov > OVF_MAX) nov = OVF_MAX;

    grid_barrier();   // ensure all gather writes to out are done

    {
        int gwarp = tid >> 5;
        int nwarp = nthreads >> 5;
        int lane  = threadIdx.x & 31;
        float* out = (float*)o4;
        for (int i = gwarp; i < nov; i += nwarp) {
            int2 t = g_ovf[i];
            int dr = g_deg[t.x];
            int dc = g_deg[t.y];
            float nm = (dr > 0 && dc > 0) ? rsqrtf((float)dr * (float)dc) : 0.0f;
            float4 v = x4[(size_t)t.y * D4 + lane];
            float* o = out + (size_t)t.x * D + lane * 4;
            atomicAdd(o + 0, nm * v.x);
            atomicAdd(o + 1, nm * v.y);
            atomicAdd(o + 2, nm * v.z);
            atomicAdd(o + 3, nm * v.w);
        }
    }
}

// ---------------------------------------------------------------- launch
extern "C" void kernel_launch(void* const* d_in, const int* in_sizes, int n_in,
                              void* d_out, int out_size) {
    const float* x   = (const float*)d_in[0];
    const float* eps = (const float*)d_in[1];
    const void*  ei  = d_in[2];
    float*       out = (float*)d_out;

    int n = in_sizes[0] / D;       // 100000
    int E = in_sizes[2] / 2;       // 1600000

    // Full-residency grid: all blocks co-resident -> spin barrier is safe.
    int dev = 0, sms = 0, bpm = 0;
    cudaGetDevice(&dev);
    cudaDeviceGetAttribute(&sms, cudaDevAttrMultiProcessorCount, dev);
    cudaOccupancyMaxActiveBlocksPerMultiprocessor(&bpm, k_fused, 256, 0);
    if (bpm < 1) bpm = 1;
    int blocks = sms * bpm;

    k_fused<<<blocks, 256>>>((const float4*)x, (float4*)out, eps, ei, n, E);
}

// round 15
// speedup vs baseline: 1.0787x; 1.0787x over previous
#include <cuda_runtime.h>
#include <stdint.h>

// GINGCN forward, 2 launches.
//   out[r] = (1+eps)*x[r] + dis_r * sum_{e: row==r} rsqrt(deg[col]) * x[col]
//
//   K1 build (persistent, 1 grid barrier):
//      P0 zero deg/cnt + reset ovf + dtype detect  -- barrier --
//      P1 edge pass: atomicAdd deg[col]; append col to bucket[row];
//         overflow -> global (r,c) list (OVF_MAX >= E, never dropped)
//   K2 gather (exact R7 champion geometry: 256-thr blocks, 1 warp/node,
//      unroll 4): acc = (1+eps)*x[w] + sum norm*x[col]; warps whose raw
//      cnt > CAP additionally scan the overflow list for their own row
//      (single-writer, no atomics) before the one non-atomic store.

#define N_MAX   100000
#define D       128
#define D4      (D / 4)        // 32 float4 per row
#define CAP     64
#define OVF_MAX 2000000        // >= E, so no overflow entry is ever dropped

__device__ int      g_deg[N_MAX];                  // in-degree (col counts)
__device__ int      g_cnt[N_MAX];                  // per-row bucket fill counts
__device__ int      g_bkt[(size_t)N_MAX * CAP];    // bucket: col only
__device__ int      g_is64;                        // edge dtype flag
__device__ int      g_ovf_n;                       // overflow entry count
__device__ int2     g_ovf[OVF_MAX];                // overflow: {row, col}
__device__ unsigned g_bar_cnt = 0;                 // barrier arrival counter
__device__ volatile unsigned g_bar_gen = 0;        // barrier generation (sense)

// ------------------------------------------------------- grid-wide barrier
// Sense-reversing, self-resetting; grid sized to full residency so all
// blocks are co-resident. Re-entrant across graph replays.
__device__ __forceinline__ void grid_barrier() {
    __syncthreads();
    if (threadIdx.x == 0) {
        __threadfence();
        unsigned gen = g_bar_gen;
        unsigned arrived = atomicAdd(&g_bar_cnt, 1u) + 1u;
        if (arrived == gridDim.x) {
            g_bar_cnt = 0;
            __threadfence();
            g_bar_gen = gen + 1u;          // release
        } else {
            while (g_bar_gen == gen) { }
        }
        __threadfence();
    }
    __syncthreads();
}

// ---------------------------------------------------------------- edge access
__device__ __forceinline__ int edge_val(const void* ei, size_t idx, int is64) {
    if (is64) return (int)((const long long*)ei)[idx];
    return ((const int*)ei)[idx];
}

// ---------------------------------------------------------------- K1: build
__global__ void k_build(const void* __restrict__ ei, int n, int E) {
    int tid      = blockIdx.x * blockDim.x + threadIdx.x;
    int nthreads = gridDim.x * blockDim.x;

    // P0: zero counters + detect dtype
    for (int i = tid; i < n; i += nthreads) { g_deg[i] = 0; g_cnt[i] = 0; }
    if (tid == 0) {
        g_ovf_n = 0;
        // int64 little-endian values < 2^31 -> every odd int32 word is 0.
        const int* p = (const int*)ei;
        int nz = 0;
        #pragma unroll
        for (int k = 0; k < 64; k++) nz |= p[2 * k + 1];
        g_is64 = (nz == 0) ? 1 : 0;
    }
    grid_barrier();

    // P1: one edge pass (degree count + bucket append, independent)
    int is64 = g_is64;
    for (int e = tid; e < E; e += nthreads) {
        int r = edge_val(ei, (size_t)e, is64);
        int c = edge_val(ei, (size_t)E + e, is64);
        atomicAdd(&g_deg[c], 1);
        int slot = atomicAdd(&g_cnt[r], 1);
        if (slot < CAP) {
            g_bkt[(size_t)r * CAP + slot] = c;
        } else {
            int o = atomicAdd(&g_ovf_n, 1);
            if (o < OVF_MAX) g_ovf[o] = make_int2(r, c);
        }
    }
}

// ---------------------------------------------------------------- K2: gather
// out[w] = (1+eps)*x[w] + dis_w * sum rsqrt(deg[c]) * x[c]
// deg[c] >= 1 guaranteed for any recorded edge (the edge itself counted).
__global__ void __launch_bounds__(256)
k_gather(const float4* __restrict__ x4, float4* __restrict__ o4,
         const float* __restrict__ eps, int n) {
    int w    = (blockIdx.x * blockDim.x + threadIdx.x) >> 5;
    int lane = threadIdx.x & 31;
    if (w >= n) return;

    int cnt_raw = g_cnt[w];
    int cnt = cnt_raw > CAP ? CAP : cnt_raw;

    float  s  = 1.0f + eps[0];
    float4 xv = x4[(size_t)w * D4 + lane];
    float4 acc;
    acc.x = s * xv.x; acc.y = s * xv.y; acc.z = s * xv.z; acc.w = s * xv.w;

    int   dw    = g_deg[w];
    float dis_w = (dw > 0) ? rsqrtf((float)dw) : 0.0f;

    size_t base = (size_t)w * CAP;
    for (int j0 = 0; j0 < cnt; j0 += 32) {
        int   mycol = 0;
        float mynrm = 0.0f;
        int idx = j0 + lane;
        if (idx < cnt) {
            mycol = g_bkt[base + idx];
            mynrm = dis_w * rsqrtf((float)g_deg[mycol]);
        }
        int m = min(32, cnt - j0);

        #pragma unroll 4
        for (int j = 0; j < m; j++) {
            int   c  = __shfl_sync(0xffffffffu, mycol, j);
            float nm = __shfl_sync(0xffffffffu, mynrm, j);
            float4 v = x4[(size_t)c * D4 + lane];
            acc.x += nm * v.x;
            acc.y += nm * v.y;
            acc.z += nm * v.z;
            acc.w += nm * v.w;
        }
    }

    // Overflow (owner-local, single-writer): scan the list for this row's
    // entries. Taken only when cnt_raw > CAP — statistically never at mean
    // degree 16, but unconditionally correct (OVF_MAX >= E).
    if (cnt_raw > CAP) {
        int nov = g_ovf_n;
        if (nov > OVF_MAX) nov = OVF_MAX;
        for (int i = 0; i < nov; i++) {
            int2 t = g_ovf[i];          // warp-uniform broadcast load
            if (t.x == w) {
                float nm = dis_w * rsqrtf((float)g_deg[t.y]);
                float4 v = x4[(size_t)t.y * D4 + lane];
                acc.x += nm * v.x;
                acc.y += nm * v.y;
                acc.z += nm * v.z;
                acc.w += nm * v.w;
            }
        }
    }

    o4[(size_t)w * D4 + lane] = acc;
}

// ---------------------------------------------------------------- launch
extern "C" void kernel_launch(void* const* d_in, const int* in_sizes, int n_in,
                              void* d_out, int out_size) {
    const float* x   = (const float*)d_in[0];
    const float* eps = (const float*)d_in[1];
    const void*  ei  = d_in[2];
    float*       out = (float*)d_out;

    int n = in_sizes[0] / D;       // 100000
    int E = in_sizes[2] / 2;       // 1600000

    // Full-residency grid for the barrier kernel.
    int dev = 0, sms = 0, bpm = 0;
    cudaGetDevice(&dev);
    cudaDeviceGetAttribute(&sms, cudaDevAttrMultiProcessorCount, dev);
    cudaOccupancyMaxActiveBlocksPerMultiprocessor(&bpm, k_build, 256, 0);
    if (bpm < 1) bpm = 1;
    int bblocks = sms * bpm;

    k_build <<<bblocks, 256>>>(ei, n, E);
    k_gather<<<(n * 32 + 255) / 256, 256>>>((const float4*)x, (float4*)out, eps, n);
}